// round 2
// baseline (speedup 1.0000x reference)
#include <cuda_runtime.h>
#include <math.h>
#include <stdint.h>

#define XD   50      // channels
#define LEN  230     // sequence length
#define LP   233     // padded smem row stride (coprime with 32 -> no bank conflicts)
#define KF   150     // flat feature dim = 3 * XD
#define NOUT 1380    // Y_DIM * SEQ_LEN = 6 * 230
#define BM   64
#define BN   64
#define KT   75      // K-chunk for GEMM (2 chunks of 75 = 150)

// Scratch for the per-batch pooled features (allocation-free rule -> device global)
__device__ float g_flat[16384 * KF];

// ---------------------------------------------------------------------------
// Stage 1: depthwise conv (k=3,6,12) + global max pool + bias -> flat[B,150]
// One CTA per batch. Transpose [L,C] -> smem [C][LP], one warp per channel.
// ---------------------------------------------------------------------------
__global__ __launch_bounds__(256) void conv_max_kernel(
    const float* __restrict__ seq,
    const float* __restrict__ w1, const float* __restrict__ b1,
    const float* __restrict__ w2, const float* __restrict__ b2,
    const float* __restrict__ w3, const float* __restrict__ b3)
{
    __shared__ float tile[XD * LP];  // 46.6 KB

    const int b   = blockIdx.x;
    const int tid = threadIdx.x;
    const float* x = seq + (size_t)b * (LEN * XD);

    // Coalesced global read, transposed smem write (stride LP=233 -> conflict-free)
    for (int i = tid; i < LEN * XD; i += 256) {
        int l = i / XD;
        int c = i - l * XD;
        tile[c * LP + l] = x[i];
    }
    __syncthreads();

    const int warp = tid >> 5;
    const int lane = tid & 31;

    for (int c = warp; c < XD; c += 8) {
        float wa[3], wb[6], wc[12];
        #pragma unroll
        for (int i = 0; i < 3;  i++) wa[i] = w1[3  * c + i];
        #pragma unroll
        for (int i = 0; i < 6;  i++) wb[i] = w2[6  * c + i];
        #pragma unroll
        for (int i = 0; i < 12; i++) wc[i] = w3[12 * c + i];

        const float* row = tile + c * LP;
        float m1 = -INFINITY, m2 = -INFINITY, m3 = -INFINITY;

        for (int p = lane; p < LEN - 2; p += 32) {
            float s1 = fmaf(row[p + 2], wa[2], fmaf(row[p + 1], wa[1], row[p] * wa[0]));
            m1 = fmaxf(m1, s1);
            if (p < LEN - 5) {
                float s2 = row[p] * wb[0];
                #pragma unroll
                for (int i = 1; i < 6; i++) s2 = fmaf(row[p + i], wb[i], s2);
                m2 = fmaxf(m2, s2);
                if (p < LEN - 11) {
                    float s3 = row[p] * wc[0];
                    #pragma unroll
                    for (int i = 1; i < 12; i++) s3 = fmaf(row[p + i], wc[i], s3);
                    m3 = fmaxf(m3, s3);
                }
            }
        }

        #pragma unroll
        for (int o = 16; o; o >>= 1) {
            m1 = fmaxf(m1, __shfl_xor_sync(0xffffffffu, m1, o));
            m2 = fmaxf(m2, __shfl_xor_sync(0xffffffffu, m2, o));
            m3 = fmaxf(m3, __shfl_xor_sync(0xffffffffu, m3, o));
        }
        if (lane == 0) {
            float* dst = g_flat + (size_t)b * KF + 3 * c;
            dst[0] = m1 + b1[c];
            dst[1] = m2 + b2[c];
            dst[2] = m3 + b3[c];
        }
    }
}

// ---------------------------------------------------------------------------
// Stage 2: out[b, o] = flat[b, :] . w_out[o, :] + b_out[o]
// M=B, N=1380, K=150. 64x64 tiles, 256 threads, 4x4 microtile, K in 2x75 chunks.
// ---------------------------------------------------------------------------
__global__ __launch_bounds__(256) void gemm_kernel(
    const float* __restrict__ W,     // [NOUT, KF]
    const float* __restrict__ bias,  // [NOUT]
    float* __restrict__ out,         // [B, NOUT]
    int nbat)
{
    __shared__ float As[KT * BM];  // [k][m], 19.2 KB
    __shared__ float Bs[KT * BN];  // [k][n], 19.2 KB

    const int bm  = blockIdx.y * BM;
    const int bn  = blockIdx.x * BN;
    const int tid = threadIdx.x;
    const int tx  = tid & 15;   // -> n
    const int ty  = tid >> 4;   // -> m

    float acc[4][4] = {};

    const float* A = g_flat;

    for (int kc = 0; kc < KF; kc += KT) {
        if (kc) __syncthreads();
        // As[k][m]: consecutive threads vary m -> conflict-free stores
        for (int i = tid; i < BM * KT; i += 256) {
            int m = i & (BM - 1), k = i >> 6;
            int gm = bm + m;
            As[k * BM + m] = (gm < nbat) ? A[(size_t)gm * KF + kc + k] : 0.f;
        }
        for (int i = tid; i < BN * KT; i += 256) {
            int n = i & (BN - 1), k = i >> 6;
            int gn = bn + n;
            Bs[k * BN + n] = (gn < NOUT) ? W[(size_t)gn * KF + kc + k] : 0.f;
        }
        __syncthreads();

        const float* ap = As + 4 * ty;
        const float* bp = Bs + 4 * tx;
        #pragma unroll 5
        for (int k = 0; k < KT; k++) {
            float4 a = *(const float4*)(ap + k * BM);
            float4 b = *(const float4*)(bp + k * BN);
            float av[4] = {a.x, a.y, a.z, a.w};
            float bv[4] = {b.x, b.y, b.z, b.w};
            #pragma unroll
            for (int i = 0; i < 4; i++)
                #pragma unroll
                for (int j = 0; j < 4; j++)
                    acc[i][j] = fmaf(av[i], bv[j], acc[i][j]);
        }
    }

    const int gn0 = bn + 4 * tx;
    if (gn0 < NOUT) {
        float4 bb = *(const float4*)(bias + gn0);
        #pragma unroll
        for (int i = 0; i < 4; i++) {
            int gm = bm + 4 * ty + i;
            if (gm < nbat) {
                float4 v;
                v.x = acc[i][0] + bb.x;
                v.y = acc[i][1] + bb.y;
                v.z = acc[i][2] + bb.z;
                v.w = acc[i][3] + bb.w;
                *(float4*)(out + (size_t)gm * NOUT + gn0) = v;
            }
        }
    }
}

// ---------------------------------------------------------------------------
extern "C" void kernel_launch(void* const* d_in, const int* in_sizes, int n_in,
                              void* d_out, int out_size)
{
    const float* seq   = (const float*)d_in[0];
    const float* w1    = (const float*)d_in[1];
    const float* b1    = (const float*)d_in[2];
    const float* w2    = (const float*)d_in[3];
    const float* b2    = (const float*)d_in[4];
    const float* w3    = (const float*)d_in[5];
    const float* b3    = (const float*)d_in[6];
    const float* w_out = (const float*)d_in[7];
    const float* b_out = (const float*)d_in[8];
    float* out = (float*)d_out;

    const int B = in_sizes[0] / (LEN * XD);

    conv_max_kernel<<<B, 256>>>(seq, w1, b1, w2, b2, w3, b3);

    dim3 grid((NOUT + BN - 1) / BN, (B + BM - 1) / BM);
    gemm_kernel<<<grid, 256>>>(w_out, b_out, out, B);
}

// round 3
// speedup vs baseline: 1.7371x; 1.7371x over previous
#include <cuda_runtime.h>
#include <math.h>
#include <stdint.h>

#define XD   50      // channels
#define LEN  230     // sequence length
#define KF   150     // flat feature dim = 3 * XD
#define NOUT 1380    // Y_DIM * SEQ_LEN
#define BM   64
#define BN   64
#define KT   75      // GEMM K-chunk (2 chunks of 75)

typedef unsigned long long ull;

__device__ float g_flat[16384 * KF];

// ---------------- packed f32x2 helpers ----------------
__device__ __forceinline__ ull pk(float lo, float hi) {
    ull r; asm("mov.b64 %0, {%1, %2};" : "=l"(r) : "f"(lo), "f"(hi)); return r;
}
__device__ __forceinline__ void unpk(ull v, float& lo, float& hi) {
    asm("mov.b64 {%0, %1}, %2;" : "=f"(lo), "=f"(hi) : "l"(v));
}
__device__ __forceinline__ ull fma2(ull a, ull b, ull c) {
    ull d; asm("fma.rn.f32x2 %0, %1, %2, %3;" : "=l"(d) : "l"(a), "l"(b), "l"(c)); return d;
}
__device__ __forceinline__ ull mul2(ull a, ull b) {
    ull d; asm("mul.rn.f32x2 %0, %1, %2;" : "=l"(d) : "l"(a), "l"(b)); return d;
}

// ---------------------------------------------------------------------------
// Stage 1: depthwise conv (k=3,6,12) + global max + bias, register ring buffer,
// two channels per thread packed as f32x2. No shared memory, no LDS.
// Thread t -> (b = t/25, cp = t%25); channels c0 = cp, c1 = cp + 25.
// ---------------------------------------------------------------------------
template<int LM, bool C1, bool C2, bool C3>
__device__ __forceinline__ void conv_step(
    const float* __restrict__ base, int l, ull (&ring)[12],
    const ull* __restrict__ wa, const ull* __restrict__ wb, const ull* __restrict__ wc,
    float& m1a, float& m1b, float& m2a, float& m2b, float& m3a, float& m3b)
{
    float a0 = __ldg(base + l * XD);
    float a1 = __ldg(base + l * XD + 25);
    ring[LM] = pk(a0, a1);
    float x, y;
    if (C1) {  // window x[l-2..l] -> ring[(LM+10+i)%12]
        ull s = mul2(wa[0], ring[(LM + 10) % 12]);
        s = fma2(wa[1], ring[(LM + 11) % 12], s);
        s = fma2(wa[2], ring[LM], s);
        unpk(s, x, y); m1a = fmaxf(m1a, x); m1b = fmaxf(m1b, y);
    }
    if (C2) {  // window x[l-5..l] -> ring[(LM+7+i)%12]
        ull s = mul2(wb[0], ring[(LM + 7) % 12]);
        #pragma unroll
        for (int i = 1; i < 6; i++) s = fma2(wb[i], ring[(LM + 7 + i) % 12], s);
        unpk(s, x, y); m2a = fmaxf(m2a, x); m2b = fmaxf(m2b, y);
    }
    if (C3) {  // window x[l-11..l] -> ring[(LM+1+i)%12]
        ull s = mul2(wc[0], ring[(LM + 1) % 12]);
        #pragma unroll
        for (int i = 1; i < 12; i++) s = fma2(wc[i], ring[(LM + 1 + i) % 12], s);
        unpk(s, x, y); m3a = fmaxf(m3a, x); m3b = fmaxf(m3b, y);
    }
}

__global__ __launch_bounds__(256) void conv_max_kernel(
    const float* __restrict__ seq,
    const float* __restrict__ w1, const float* __restrict__ b1,
    const float* __restrict__ w2, const float* __restrict__ b2,
    const float* __restrict__ w3, const float* __restrict__ b3,
    int nthreads)
{
    const int t = blockIdx.x * 256 + threadIdx.x;
    if (t >= nthreads) return;
    const int b  = t / 25;
    const int cp = t - b * 25;
    const int c0 = cp, c1 = cp + 25;

    const float* base = seq + (size_t)b * (LEN * XD) + c0;

    ull wa[3], wb[6], wc[12];
    #pragma unroll
    for (int i = 0; i < 3;  i++) wa[i] = pk(w1[3 * c0 + i],  w1[3 * c1 + i]);
    #pragma unroll
    for (int i = 0; i < 6;  i++) wb[i] = pk(w2[6 * c0 + i],  w2[6 * c1 + i]);
    #pragma unroll
    for (int i = 0; i < 12; i++) wc[i] = pk(w3[12 * c0 + i], w3[12 * c1 + i]);

    ull ring[12];
    float m1a = -INFINITY, m1b = -INFINITY;
    float m2a = -INFINITY, m2b = -INFINITY;
    float m3a = -INFINITY, m3b = -INFINITY;

    #define STEP(LM,C1F,C2F,C3F,L) \
        conv_step<LM,C1F,C2F,C3F>(base, L, ring, wa, wb, wc, m1a,m1b,m2a,m2b,m3a,m3b)

    // prologue l = 0..10
    STEP(0,  false, false, false, 0);
    STEP(1,  false, false, false, 1);
    STEP(2,  true,  false, false, 2);
    STEP(3,  true,  false, false, 3);
    STEP(4,  true,  false, false, 4);
    STEP(5,  true,  true,  false, 5);
    STEP(6,  true,  true,  false, 6);
    STEP(7,  true,  true,  false, 7);
    STEP(8,  true,  true,  false, 8);
    STEP(9,  true,  true,  false, 9);
    STEP(10, true,  true,  false, 10);

    // main: l = 11 .. 226 in chunks of 12 (base%12 == 11 throughout)
    int l = 11;
    for (; l + 12 <= LEN; l += 12) {
        STEP(11, true, true, true, l + 0);
        STEP(0,  true, true, true, l + 1);
        STEP(1,  true, true, true, l + 2);
        STEP(2,  true, true, true, l + 3);
        STEP(3,  true, true, true, l + 4);
        STEP(4,  true, true, true, l + 5);
        STEP(5,  true, true, true, l + 6);
        STEP(6,  true, true, true, l + 7);
        STEP(7,  true, true, true, l + 8);
        STEP(8,  true, true, true, l + 9);
        STEP(9,  true, true, true, l + 10);
        STEP(10, true, true, true, l + 11);
    }
    // tail l = 227, 228, 229  (227%12=11, 228%12=0, 229%12=1)
    STEP(11, true, true, true, 227);
    STEP(0,  true, true, true, 228);
    STEP(1,  true, true, true, 229);
    #undef STEP

    float* dst = g_flat + (size_t)b * KF;
    dst[3 * c0 + 0] = m1a + b1[c0];
    dst[3 * c0 + 1] = m2a + b2[c0];
    dst[3 * c0 + 2] = m3a + b3[c0];
    dst[3 * c1 + 0] = m1b + b1[c1];
    dst[3 * c1 + 1] = m2b + b2[c1];
    dst[3 * c1 + 2] = m3b + b3[c1];
}

// ---------------------------------------------------------------------------
// Stage 2 GEMM: out[b,o] = flat[b,:] . W[o,:] + bias[o]
// 64x64 tile, 256 threads, 4x4 microtile with packed f32x2 accumulation.
// ---------------------------------------------------------------------------
__global__ __launch_bounds__(256) void gemm_kernel(
    const float* __restrict__ W,     // [NOUT, KF]
    const float* __restrict__ bias,  // [NOUT]
    float* __restrict__ out,         // [B, NOUT]
    int nbat)
{
    __shared__ float As[KT * BM];  // [k][m]
    __shared__ float Bs[KT * BN];  // [k][n]

    const int bm  = blockIdx.y * BM;
    const int bn  = blockIdx.x * BN;
    const int tid = threadIdx.x;
    const int tx  = tid & 15;   // -> n (4 cols)
    const int ty  = tid >> 4;   // -> m (4 rows)

    ull accp[4][2] = {};        // (0ull == packed {0.f,0.f})

    const float* A = g_flat;

    for (int kc = 0; kc < KF; kc += KT) {
        if (kc) __syncthreads();
        for (int i = tid; i < BM * KT; i += 256) {
            int m = i & (BM - 1), k = i >> 6;
            int gm = bm + m;
            As[k * BM + m] = (gm < nbat) ? A[(size_t)gm * KF + kc + k] : 0.f;
        }
        for (int i = tid; i < BN * KT; i += 256) {
            int n = i & (BN - 1), k = i >> 6;
            int gn = bn + n;
            Bs[k * BN + n] = (gn < NOUT) ? W[(size_t)gn * KF + kc + k] : 0.f;
        }
        __syncthreads();

        const float* ap = As + 4 * ty;
        const float* bp = Bs + 4 * tx;
        #pragma unroll 5
        for (int k = 0; k < KT; k++) {
            float4 a = *(const float4*)(ap + k * BM);
            ulonglong2 bv = *(const ulonglong2*)(bp + k * BN);
            ull a0 = pk(a.x, a.x);
            ull a1 = pk(a.y, a.y);
            ull a2 = pk(a.z, a.z);
            ull a3 = pk(a.w, a.w);
            accp[0][0] = fma2(a0, bv.x, accp[0][0]);
            accp[0][1] = fma2(a0, bv.y, accp[0][1]);
            accp[1][0] = fma2(a1, bv.x, accp[1][0]);
            accp[1][1] = fma2(a1, bv.y, accp[1][1]);
            accp[2][0] = fma2(a2, bv.x, accp[2][0]);
            accp[2][1] = fma2(a2, bv.y, accp[2][1]);
            accp[3][0] = fma2(a3, bv.x, accp[3][0]);
            accp[3][1] = fma2(a3, bv.y, accp[3][1]);
        }
    }

    const int gn0 = bn + 4 * tx;
    if (gn0 < NOUT) {
        float4 bb = *(const float4*)(bias + gn0);
        #pragma unroll
        for (int i = 0; i < 4; i++) {
            int gm = bm + 4 * ty + i;
            if (gm < nbat) {
                float f0, f1, f2, f3;
                unpk(accp[i][0], f0, f1);
                unpk(accp[i][1], f2, f3);
                float4 v;
                v.x = f0 + bb.x;
                v.y = f1 + bb.y;
                v.z = f2 + bb.z;
                v.w = f3 + bb.w;
                *(float4*)(out + (size_t)gm * NOUT + gn0) = v;
            }
        }
    }
}

// ---------------------------------------------------------------------------
extern "C" void kernel_launch(void* const* d_in, const int* in_sizes, int n_in,
                              void* d_out, int out_size)
{
    const float* seq   = (const float*)d_in[0];
    const float* w1    = (const float*)d_in[1];
    const float* b1    = (const float*)d_in[2];
    const float* w2    = (const float*)d_in[3];
    const float* b2    = (const float*)d_in[4];
    const float* w3    = (const float*)d_in[5];
    const float* b3    = (const float*)d_in[6];
    const float* w_out = (const float*)d_in[7];
    const float* b_out = (const float*)d_in[8];
    float* out = (float*)d_out;

    const int B = in_sizes[0] / (LEN * XD);
    const int nthreads = B * 25;   // one thread per (batch, channel-pair)

    conv_max_kernel<<<(nthreads + 255) / 256, 256>>>(seq, w1, b1, w2, b2, w3, b3, nthreads);

    dim3 grid((NOUT + BN - 1) / BN, (B + BM - 1) / BM);
    gemm_kernel<<<grid, 256>>>(w_out, b_out, out, B);
}

// round 4
// speedup vs baseline: 2.1143x; 1.2171x over previous
#include <cuda_runtime.h>
#include <math.h>
#include <stdint.h>

#define XD    50      // channels
#define LEN   230     // sequence length
#define KF    150     // flat feature dim = 3 * XD
#define NOUT  1380    // Y_DIM * SEQ_LEN
#define BTOT  16384   // max batch
#define NPAD  1408    // NOUT padded to multiple of 128

// GEMM tiling
#define GBM 128
#define GBN 128
#define GKT 30        // 5 chunks of 30 = 150

typedef unsigned long long ull;

// flat features, TRANSPOSED: g_flatT[k][b], k in [0,150), stride BTOT
__device__ __align__(16) float g_flatT[KF * BTOT];
// w_out transposed + padded: g_WT[k][n], stride NPAD
__device__ __align__(16) float g_WT[KF * NPAD];

// ---------------- packed f32x2 helpers ----------------
__device__ __forceinline__ ull pk(float lo, float hi) {
    ull r; asm("mov.b64 %0, {%1, %2};" : "=l"(r) : "f"(lo), "f"(hi)); return r;
}
__device__ __forceinline__ void unpk(ull v, float& lo, float& hi) {
    asm("mov.b64 {%0, %1}, %2;" : "=f"(lo), "=f"(hi) : "l"(v));
}
__device__ __forceinline__ ull fma2(ull a, ull b, ull c) {
    ull d; asm("fma.rn.f32x2 %0, %1, %2, %3;" : "=l"(d) : "l"(a), "l"(b), "l"(c)); return d;
}
__device__ __forceinline__ ull mul2(ull a, ull b) {
    ull d; asm("mul.rn.f32x2 %0, %1, %2;" : "=l"(d) : "l"(a), "l"(b)); return d;
}

// ---------------------------------------------------------------------------
// Stage 0: transpose w_out [NOUT][KF] -> g_WT [KF][NPAD] (zero padded)
// ---------------------------------------------------------------------------
__global__ __launch_bounds__(256) void wt_kernel(const float* __restrict__ W)
{
    int i = blockIdx.x * 256 + threadIdx.x;
    if (i >= KF * NPAD) return;
    int k = i / NPAD, n = i - k * NPAD;
    g_WT[i] = (n < NOUT) ? W[n * KF + k] : 0.f;
}

// ---------------------------------------------------------------------------
// Stage 1: depthwise conv (k=3,6,12) + global max + bias.
// Thread t -> (b = t/25, p = t%25); channels c0 = 2p, c1 = 2p+1 (adjacent ->
// one LDG.64 per step, loaded directly as packed f32x2). Register ring buffer.
// Writes transposed: g_flatT[(3c+j)][b].
// ---------------------------------------------------------------------------
template<int LM, bool C1, bool C2, bool C3>
__device__ __forceinline__ void conv_step(
    const float* __restrict__ base, int l, ull (&ring)[12],
    const ull* __restrict__ wa, const ull* __restrict__ wb, const ull* __restrict__ wc,
    float& m1a, float& m1b, float& m2a, float& m2b, float& m3a, float& m3b)
{
    ring[LM] = *(const ull*)(base + l * XD);   // {x[l][c0], x[l][c1]}
    float x, y;
    if (C1) {
        ull s = mul2(wa[0], ring[(LM + 10) % 12]);
        s = fma2(wa[1], ring[(LM + 11) % 12], s);
        s = fma2(wa[2], ring[LM], s);
        unpk(s, x, y); m1a = fmaxf(m1a, x); m1b = fmaxf(m1b, y);
    }
    if (C2) {
        ull s = mul2(wb[0], ring[(LM + 7) % 12]);
        #pragma unroll
        for (int i = 1; i < 6; i++) s = fma2(wb[i], ring[(LM + 7 + i) % 12], s);
        unpk(s, x, y); m2a = fmaxf(m2a, x); m2b = fmaxf(m2b, y);
    }
    if (C3) {
        ull s = mul2(wc[0], ring[(LM + 1) % 12]);
        #pragma unroll
        for (int i = 1; i < 12; i++) s = fma2(wc[i], ring[(LM + 1 + i) % 12], s);
        unpk(s, x, y); m3a = fmaxf(m3a, x); m3b = fmaxf(m3b, y);
    }
}

__global__ __launch_bounds__(256) void conv_max_kernel(
    const float* __restrict__ seq,
    const float* __restrict__ w1, const float* __restrict__ b1,
    const float* __restrict__ w2, const float* __restrict__ b2,
    const float* __restrict__ w3, const float* __restrict__ b3,
    int nthreads)
{
    const int t = blockIdx.x * 256 + threadIdx.x;
    if (t >= nthreads) return;
    const int b  = t / 25;
    const int p  = t - b * 25;
    const int c0 = 2 * p, c1 = 2 * p + 1;

    const float* base = seq + (size_t)b * (LEN * XD) + c0;  // 8B aligned (even offset)

    ull wa[3], wb[6], wc[12];
    #pragma unroll
    for (int i = 0; i < 3;  i++) wa[i] = pk(w1[3 * c0 + i],  w1[3 * c1 + i]);
    #pragma unroll
    for (int i = 0; i < 6;  i++) wb[i] = pk(w2[6 * c0 + i],  w2[6 * c1 + i]);
    #pragma unroll
    for (int i = 0; i < 12; i++) wc[i] = pk(w3[12 * c0 + i], w3[12 * c1 + i]);

    ull ring[12];
    float m1a = -INFINITY, m1b = -INFINITY;
    float m2a = -INFINITY, m2b = -INFINITY;
    float m3a = -INFINITY, m3b = -INFINITY;

    #define STEP(LM,C1F,C2F,C3F,L) \
        conv_step<LM,C1F,C2F,C3F>(base, L, ring, wa, wb, wc, m1a,m1b,m2a,m2b,m3a,m3b)

    STEP(0,  false, false, false, 0);
    STEP(1,  false, false, false, 1);
    STEP(2,  true,  false, false, 2);
    STEP(3,  true,  false, false, 3);
    STEP(4,  true,  false, false, 4);
    STEP(5,  true,  true,  false, 5);
    STEP(6,  true,  true,  false, 6);
    STEP(7,  true,  true,  false, 7);
    STEP(8,  true,  true,  false, 8);
    STEP(9,  true,  true,  false, 9);
    STEP(10, true,  true,  false, 10);

    int l = 11;
    for (; l + 12 <= LEN; l += 12) {
        STEP(11, true, true, true, l + 0);
        STEP(0,  true, true, true, l + 1);
        STEP(1,  true, true, true, l + 2);
        STEP(2,  true, true, true, l + 3);
        STEP(3,  true, true, true, l + 4);
        STEP(4,  true, true, true, l + 5);
        STEP(5,  true, true, true, l + 6);
        STEP(6,  true, true, true, l + 7);
        STEP(7,  true, true, true, l + 8);
        STEP(8,  true, true, true, l + 9);
        STEP(9,  true, true, true, l + 10);
        STEP(10, true, true, true, l + 11);
    }
    STEP(11, true, true, true, 227);
    STEP(0,  true, true, true, 228);
    STEP(1,  true, true, true, 229);
    #undef STEP

    // transposed epilogue: g_flatT[row][b]
    g_flatT[(3 * c0 + 0) * BTOT + b] = m1a + b1[c0];
    g_flatT[(3 * c0 + 1) * BTOT + b] = m2a + b2[c0];
    g_flatT[(3 * c0 + 2) * BTOT + b] = m3a + b3[c0];
    g_flatT[(3 * c1 + 0) * BTOT + b] = m1b + b1[c1];
    g_flatT[(3 * c1 + 1) * BTOT + b] = m2b + b2[c1];
    g_flatT[(3 * c1 + 2) * BTOT + b] = m3b + b3[c1];
}

// ---------------------------------------------------------------------------
// Stage 2 GEMM: out[b,n] = sum_k g_flatT[k][b] * g_WT[k][n] + bias[n]
// 128x128 tile, 256 threads, 8x8 microtile, packed f32x2, KT=30 x 5 chunks.
// Warps 4x2 (m x n), lanes 4x8 (m x n): A frag broadcasts, B spans banks.
// ---------------------------------------------------------------------------
__global__ __launch_bounds__(256, 2) void gemm_kernel(
    const float* __restrict__ bias,  // [NOUT]
    float* __restrict__ out,         // [B, NOUT]
    int nbat)
{
    __shared__ float As[GKT * GBM];  // [k][m] 15 KB
    __shared__ float Bs[GKT * GBN];  // [k][n] 15 KB

    const int bm  = blockIdx.y * GBM;
    const int bn  = blockIdx.x * GBN;
    const int tid = threadIdx.x;
    const int warp = tid >> 5, lane = tid & 31;
    const int wm = warp & 3, wn = warp >> 2;     // 4 x 2 warps
    const int lm = lane & 3, ln = lane >> 2;     // 4 x 8 lanes
    const int m0 = wm * 32 + lm * 8;
    const int n0 = wn * 64 + ln * 8;

    ull acc[8][4] = {};

    for (int kc = 0; kc < KF; kc += GKT) {
        if (kc) __syncthreads();
        #pragma unroll
        for (int i = tid; i < GKT * 32; i += 256) {   // 960 float4 copies each
            int k = i >> 5, mv = (i & 31) << 2;
            *(float4*)(As + k * GBM + mv) =
                *(const float4*)(g_flatT + (size_t)(kc + k) * BTOT + bm + mv);
            *(float4*)(Bs + k * GBN + mv) =
                *(const float4*)(g_WT + (kc + k) * NPAD + bn + mv);
        }
        __syncthreads();

        const float* ap = As + m0;
        const float* bp = Bs + n0;
        #pragma unroll 6
        for (int k = 0; k < GKT; k++) {
            float4 a0 = *(const float4*)(ap + k * GBM);
            float4 a1 = *(const float4*)(ap + k * GBM + 4);
            ulonglong2 bv0 = *(const ulonglong2*)(bp + k * GBN);
            ulonglong2 bv1 = *(const ulonglong2*)(bp + k * GBN + 4);
            ull av[8];
            av[0] = pk(a0.x, a0.x); av[1] = pk(a0.y, a0.y);
            av[2] = pk(a0.z, a0.z); av[3] = pk(a0.w, a0.w);
            av[4] = pk(a1.x, a1.x); av[5] = pk(a1.y, a1.y);
            av[6] = pk(a1.z, a1.z); av[7] = pk(a1.w, a1.w);
            ull bb[4] = {bv0.x, bv0.y, bv1.x, bv1.y};
            #pragma unroll
            for (int i = 0; i < 8; i++)
                #pragma unroll
                for (int j = 0; j < 4; j++)
                    acc[i][j] = fma2(av[i], bb[j], acc[i][j]);
        }
    }

    const int gn0 = bn + n0;
    const int gm0 = bm + m0;
    if (gn0 + 8 <= NOUT) {
        float4 bb0 = *(const float4*)(bias + gn0);
        float4 bb1 = *(const float4*)(bias + gn0 + 4);
        #pragma unroll
        for (int i = 0; i < 8; i++) {
            int gm = gm0 + i;
            if (gm < nbat) {
                float f[8];
                unpk(acc[i][0], f[0], f[1]);
                unpk(acc[i][1], f[2], f[3]);
                unpk(acc[i][2], f[4], f[5]);
                unpk(acc[i][3], f[6], f[7]);
                float4 v0 = {f[0] + bb0.x, f[1] + bb0.y, f[2] + bb0.z, f[3] + bb0.w};
                float4 v1 = {f[4] + bb1.x, f[5] + bb1.y, f[6] + bb1.z, f[7] + bb1.w};
                float* o = out + (size_t)gm * NOUT + gn0;
                *(float4*)o = v0;
                *(float4*)(o + 4) = v1;
            }
        }
    } else if (gn0 < NOUT) {
        #pragma unroll
        for (int i = 0; i < 8; i++) {
            int gm = gm0 + i;
            if (gm < nbat) {
                float f[8];
                unpk(acc[i][0], f[0], f[1]);
                unpk(acc[i][1], f[2], f[3]);
                unpk(acc[i][2], f[4], f[5]);
                unpk(acc[i][3], f[6], f[7]);
                for (int j = 0; j < 8; j++) {
                    int gn = gn0 + j;
                    if (gn < NOUT) out[(size_t)gm * NOUT + gn] = f[j] + bias[gn];
                }
            }
        }
    }
}

// ---------------------------------------------------------------------------
extern "C" void kernel_launch(void* const* d_in, const int* in_sizes, int n_in,
                              void* d_out, int out_size)
{
    const float* seq   = (const float*)d_in[0];
    const float* w1    = (const float*)d_in[1];
    const float* b1    = (const float*)d_in[2];
    const float* w2    = (const float*)d_in[3];
    const float* b2    = (const float*)d_in[4];
    const float* w3    = (const float*)d_in[5];
    const float* b3    = (const float*)d_in[6];
    const float* w_out = (const float*)d_in[7];
    const float* b_out = (const float*)d_in[8];
    float* out = (float*)d_out;

    const int B = in_sizes[0] / (LEN * XD);
    const int nthreads = B * 25;

    wt_kernel<<<(KF * NPAD + 255) / 256, 256>>>(w_out);
    conv_max_kernel<<<(nthreads + 255) / 256, 256>>>(seq, w1, b1, w2, b2, w3, b3, nthreads);

    dim3 grid((NOUT + GBN - 1) / GBN, (B + GBM - 1) / GBM);
    gemm_kernel<<<grid, 256>>>(b_out, out, B);
}

// round 6
// speedup vs baseline: 2.5174x; 1.1906x over previous
#include <cuda_runtime.h>
#include <math.h>
#include <stdint.h>

#define XD    50
#define LEN   230
#define KF    150
#define KSTEPS 20          // K padded to 160 = 20 x 8
#define NOUT  1380
#define NP    1408         // N padded to 11 x 128
#define BTOT  16384

typedef unsigned long long ull;

// A in fragment-major layout: [mtile(16 rows)][kstep(8 cols)][lane*4+slot]
__device__ __align__(16) float g_flatF[(BTOT / 16) * KSTEPS * 128];
// B in fragment-major layout: [n8tile][kstep][lane*2+slot]
__device__ __align__(16) float g_WF[(NP / 8) * KSTEPS * 64];

// ---------------- helpers ----------------
__device__ __forceinline__ ull pk(float lo, float hi) {
    ull r; asm("mov.b64 %0, {%1, %2};" : "=l"(r) : "f"(lo), "f"(hi)); return r;
}
__device__ __forceinline__ void unpk(ull v, float& lo, float& hi) {
    asm("mov.b64 {%0, %1}, %2;" : "=f"(lo), "=f"(hi) : "l"(v));
}
__device__ __forceinline__ ull fma2(ull a, ull b, ull c) {
    ull d; asm("fma.rn.f32x2 %0, %1, %2, %3;" : "=l"(d) : "l"(a), "l"(b), "l"(c)); return d;
}
__device__ __forceinline__ ull mul2(ull a, ull b) {
    ull d; asm("mul.rn.f32x2 %0, %1, %2;" : "=l"(d) : "l"(a), "l"(b)); return d;
}
__device__ __forceinline__ float tf32r(float x) {
    unsigned u; asm("cvt.rna.tf32.f32 %0, %1;" : "=r"(u) : "f"(x));
    return __uint_as_float(u);
}

// fragment-major index for A element (b, k)
__device__ __forceinline__ int a_idx(int b, int k) {
    int mt = b >> 4, row = b & 15, ks = k >> 3, kc = k & 7;
    int lane = ((row & 7) << 2) | (kc & 3);
    int slot = ((kc >> 2) << 1) | (row >> 3);
    return (mt * KSTEPS + ks) * 128 + lane * 4 + slot;
}

// ---------------------------------------------------------------------------
// Stage 0: w_out [NOUT][KF] -> g_WF fragment-major (tf32-rounded, zero pad)
// ---------------------------------------------------------------------------
__global__ __launch_bounds__(256) void wt_kernel(const float* __restrict__ W)
{
    int i = blockIdx.x * 256 + threadIdx.x;
    if (i >= (NP / 8) * KSTEPS * 64) return;
    int n8 = i / (KSTEPS * 64);
    int r  = i - n8 * (KSTEPS * 64);
    int ks = r >> 6, q = r & 63;
    int lane = q >> 1, slot = q & 1;
    int n = n8 * 8 + (lane >> 2);
    int k = ks * 8 + (lane & 3) + 4 * slot;
    g_WF[i] = (n < NOUT && k < KF) ? tf32r(W[n * KF + k]) : 0.f;
}

// ---------------------------------------------------------------------------
// Stage 1: depthwise conv (k=3,6,12) + max + bias -> g_flatF (fragment-major)
// ---------------------------------------------------------------------------
template<int LM, bool C1, bool C2, bool C3>
__device__ __forceinline__ void conv_step(
    const float* __restrict__ base, int l, ull (&ring)[12],
    const ull* __restrict__ wa, const ull* __restrict__ wb, const ull* __restrict__ wc,
    float& m1a, float& m1b, float& m2a, float& m2b, float& m3a, float& m3b)
{
    ring[LM] = *(const ull*)(base + l * XD);
    float x, y;
    if (C1) {
        ull s = mul2(wa[0], ring[(LM + 10) % 12]);
        s = fma2(wa[1], ring[(LM + 11) % 12], s);
        s = fma2(wa[2], ring[LM], s);
        unpk(s, x, y); m1a = fmaxf(m1a, x); m1b = fmaxf(m1b, y);
    }
    if (C2) {
        ull s = mul2(wb[0], ring[(LM + 7) % 12]);
        #pragma unroll
        for (int i = 1; i < 6; i++) s = fma2(wb[i], ring[(LM + 7 + i) % 12], s);
        unpk(s, x, y); m2a = fmaxf(m2a, x); m2b = fmaxf(m2b, y);
    }
    if (C3) {
        ull s = mul2(wc[0], ring[(LM + 1) % 12]);
        #pragma unroll
        for (int i = 1; i < 12; i++) s = fma2(wc[i], ring[(LM + 1 + i) % 12], s);
        unpk(s, x, y); m3a = fmaxf(m3a, x); m3b = fmaxf(m3b, y);
    }
}

__global__ __launch_bounds__(256) void conv_max_kernel(
    const float* __restrict__ seq,
    const float* __restrict__ w1, const float* __restrict__ b1,
    const float* __restrict__ w2, const float* __restrict__ b2,
    const float* __restrict__ w3, const float* __restrict__ b3,
    int nthreads)
{
    const int t = blockIdx.x * 256 + threadIdx.x;
    if (t >= nthreads) return;
    const int b  = t / 25;
    const int p  = t - b * 25;
    const int c0 = 2 * p, c1 = 2 * p + 1;

    const float* base = seq + (size_t)b * (LEN * XD) + c0;

    ull wa[3], wb[6], wc[12];
    #pragma unroll
    for (int i = 0; i < 3;  i++) wa[i] = pk(w1[3 * c0 + i],  w1[3 * c1 + i]);
    #pragma unroll
    for (int i = 0; i < 6;  i++) wb[i] = pk(w2[6 * c0 + i],  w2[6 * c1 + i]);
    #pragma unroll
    for (int i = 0; i < 12; i++) wc[i] = pk(w3[12 * c0 + i], w3[12 * c1 + i]);

    ull ring[12];
    float m1a = -INFINITY, m1b = -INFINITY;
    float m2a = -INFINITY, m2b = -INFINITY;
    float m3a = -INFINITY, m3b = -INFINITY;

    #define STEP(LM,C1F,C2F,C3F,L) \
        conv_step<LM,C1F,C2F,C3F>(base, L, ring, wa, wb, wc, m1a,m1b,m2a,m2b,m3a,m3b)

    STEP(0,  false, false, false, 0);
    STEP(1,  false, false, false, 1);
    STEP(2,  true,  false, false, 2);
    STEP(3,  true,  false, false, 3);
    STEP(4,  true,  false, false, 4);
    STEP(5,  true,  true,  false, 5);
    STEP(6,  true,  true,  false, 6);
    STEP(7,  true,  true,  false, 7);
    STEP(8,  true,  true,  false, 8);
    STEP(9,  true,  true,  false, 9);
    STEP(10, true,  true,  false, 10);

    int l = 11;
    for (; l + 12 <= LEN; l += 12) {
        STEP(11, true, true, true, l + 0);
        STEP(0,  true, true, true, l + 1);
        STEP(1,  true, true, true, l + 2);
        STEP(2,  true, true, true, l + 3);
        STEP(3,  true, true, true, l + 4);
        STEP(4,  true, true, true, l + 5);
        STEP(5,  true, true, true, l + 6);
        STEP(6,  true, true, true, l + 7);
        STEP(7,  true, true, true, l + 8);
        STEP(8,  true, true, true, l + 9);
        STEP(9,  true, true, true, l + 10);
        STEP(10, true, true, true, l + 11);
    }
    STEP(11, true, true, true, 227);
    STEP(0,  true, true, true, 228);
    STEP(1,  true, true, true, 229);
    #undef STEP

    g_flatF[a_idx(b, 3 * c0 + 0)] = tf32r(m1a + b1[c0]);
    g_flatF[a_idx(b, 3 * c0 + 1)] = tf32r(m2a + b2[c0]);
    g_flatF[a_idx(b, 3 * c0 + 2)] = tf32r(m3a + b3[c0]);
    g_flatF[a_idx(b, 3 * c1 + 0)] = tf32r(m1b + b1[c1]);
    g_flatF[a_idx(b, 3 * c1 + 1)] = tf32r(m2b + b2[c1]);
    g_flatF[a_idx(b, 3 * c1 + 2)] = tf32r(m3b + b3[c1]);
    if (p < 5) {                       // zero-pad k = 150..159
        g_flatF[a_idx(b, KF + 2 * p)]     = 0.f;
        g_flatF[a_idx(b, KF + 2 * p + 1)] = 0.f;
    }
}

// ---------------------------------------------------------------------------
// Stage 2: tf32 mma.sync GEMM. CTA 128x128, full K (20 ksteps) in smem,
// fragment-major smem (LDS.128 per A frag, LDS.64 per B frag), 8 warps 2x4,
// warp tile 64x32 (4x4 mma tiles). Epilogue: direct float2 stores + bias.
// ---------------------------------------------------------------------------
#define SMEM_A_FLOATS (8 * KSTEPS * 128)     // 20480
#define SMEM_B_FLOATS (16 * KSTEPS * 64)     // 20480
#define SMEM_SZ ((SMEM_A_FLOATS + SMEM_B_FLOATS) * 4)   // 160 KB

__device__ __forceinline__ void mma_tf32_16n8k8(
    float& c0, float& c1, float& c2, float& c3,
    uint32_t a0, uint32_t a1, uint32_t a2, uint32_t a3,
    uint32_t b0, uint32_t b1)
{
    asm volatile(
        "mma.sync.aligned.m16n8k8.row.col.f32.tf32.tf32.f32 "
        "{%0,%1,%2,%3}, {%4,%5,%6,%7}, {%8,%9}, {%0,%1,%2,%3};"
        : "+f"(c0), "+f"(c1), "+f"(c2), "+f"(c3)
        : "r"(a0), "r"(a1), "r"(a2), "r"(a3), "r"(b0), "r"(b1));
}

__global__ __launch_bounds__(256, 1)
void mma_kernel(const float* __restrict__ bias, float* __restrict__ out, int nbat)
{
    extern __shared__ float smem[];
    float* sA = smem;
    float* sB = smem + SMEM_A_FLOATS;

    const int tid  = threadIdx.x;
    const int warp = tid >> 5, lane = tid & 31;
    const int wm = warp & 1, wn = warp >> 1;   // 2 x 4 warps
    const int bm = blockIdx.y * 128, bn = blockIdx.x * 128;

    // bulk coalesced copies (both source slabs are contiguous)
    {
        const float4* gA = (const float4*)(g_flatF + (size_t)(bm >> 4) * KSTEPS * 128);
        const float4* gB = (const float4*)(g_WF    + (size_t)(bn >> 3) * KSTEPS * 64);
        float4* dA = (float4*)sA;
        float4* dB = (float4*)sB;
        #pragma unroll
        for (int i = tid; i < SMEM_A_FLOATS / 4; i += 256) {
            dA[i] = gA[i];
            dB[i] = gB[i];
        }
    }
    __syncthreads();

    float acc[4][4][4];
    #pragma unroll
    for (int i = 0; i < 4; i++)
        #pragma unroll
        for (int j = 0; j < 4; j++)
            #pragma unroll
            for (int r = 0; r < 4; r++) acc[i][j][r] = 0.f;

    #pragma unroll 4
    for (int ks = 0; ks < KSTEPS; ks++) {
        uint32_t a[4][4], b[4][2];
        #pragma unroll
        for (int mt = 0; mt < 4; mt++) {
            float4 v = *(const float4*)(sA + ((wm * 4 + mt) * KSTEPS + ks) * 128 + lane * 4);
            a[mt][0] = __float_as_uint(v.x);
            a[mt][1] = __float_as_uint(v.y);
            a[mt][2] = __float_as_uint(v.z);
            a[mt][3] = __float_as_uint(v.w);
        }
        #pragma unroll
        for (int nt = 0; nt < 4; nt++) {
            float2 v = *(const float2*)(sB + ((wn * 4 + nt) * KSTEPS + ks) * 64 + lane * 2);
            b[nt][0] = __float_as_uint(v.x);
            b[nt][1] = __float_as_uint(v.y);
        }
        #pragma unroll
        for (int mt = 0; mt < 4; mt++)
            #pragma unroll
            for (int nt = 0; nt < 4; nt++)
                mma_tf32_16n8k8(acc[mt][nt][0], acc[mt][nt][1], acc[mt][nt][2], acc[mt][nt][3],
                                a[mt][0], a[mt][1], a[mt][2], a[mt][3],
                                b[nt][0], b[nt][1]);
    }

    // epilogue: c0=(g,2t), c1=(g,2t+1), c2=(g+8,2t), c3=(g+8,2t+1)
    const int g  = lane >> 2;
    const int tg = lane & 3;
    #pragma unroll
    for (int mt = 0; mt < 4; mt++) {
        int row0 = bm + wm * 64 + mt * 16 + g;
        int row1 = row0 + 8;
        #pragma unroll
        for (int nt = 0; nt < 4; nt++) {
            int col = bn + wn * 32 + nt * 8 + 2 * tg;
            if (col < NOUT) {
                float2 bb = *(const float2*)(bias + col);
                if (row0 < nbat) {
                    float2 v = {acc[mt][nt][0] + bb.x, acc[mt][nt][1] + bb.y};
                    *(float2*)(out + (size_t)row0 * NOUT + col) = v;
                }
                if (row1 < nbat) {
                    float2 v = {acc[mt][nt][2] + bb.x, acc[mt][nt][3] + bb.y};
                    *(float2*)(out + (size_t)row1 * NOUT + col) = v;
                }
            }
        }
    }
}

// ---------------------------------------------------------------------------
extern "C" void kernel_launch(void* const* d_in, const int* in_sizes, int n_in,
                              void* d_out, int out_size)
{
    const float* seq   = (const float*)d_in[0];
    const float* w1    = (const float*)d_in[1];
    const float* b1    = (const float*)d_in[2];
    const float* w2    = (const float*)d_in[3];
    const float* b2    = (const float*)d_in[4];
    const float* w3    = (const float*)d_in[5];
    const float* b3    = (const float*)d_in[6];
    const float* w_out = (const float*)d_in[7];
    const float* b_out = (const float*)d_in[8];
    float* out = (float*)d_out;

    const int B = in_sizes[0] / (LEN * XD);
    const int nthreads = B * 25;

    static int smem_set = 0;
    if (!smem_set) {
        cudaFuncSetAttribute(mma_kernel, cudaFuncAttributeMaxDynamicSharedMemorySize, SMEM_SZ);
        smem_set = 1;
    }

    wt_kernel<<<((NP / 8) * KSTEPS * 64 + 255) / 256, 256>>>(w_out);
    conv_max_kernel<<<(nthreads + 255) / 256, 256>>>(seq, w1, b1, w2, b2, w3, b3, nthreads);

    dim3 grid(NP / 128, (B + 127) / 128);
    mma_kernel<<<grid, 256, SMEM_SZ>>>(b_out, out, B);
}

// round 7
// speedup vs baseline: 3.1646x; 1.2571x over previous
#include <cuda_runtime.h>
#include <math.h>
#include <stdint.h>

#define XD    50
#define LEN   230
#define KF    150
#define KSTEPS 20          // K padded to 160 = 20 x 8
#define NOUT  1380
#define NP    1408
#define BTOT  16384

typedef unsigned long long ull;

// A fragment-major: [mtile(16 rows)][kstep(8 cols)][lane*4+slot]
__device__ __align__(16) float g_flatF[(BTOT / 16) * KSTEPS * 128];
// B fragment-major: [n8tile][kstep][lane*2+slot]
__device__ __align__(16) float g_WF[(NP / 8) * KSTEPS * 64];

// ---------------- helpers ----------------
__device__ __forceinline__ ull pk(float lo, float hi) {
    ull r; asm("mov.b64 %0, {%1, %2};" : "=l"(r) : "f"(lo), "f"(hi)); return r;
}
__device__ __forceinline__ void unpk(ull v, float& lo, float& hi) {
    asm("mov.b64 {%0, %1}, %2;" : "=f"(lo), "=f"(hi) : "l"(v));
}
__device__ __forceinline__ ull fma2(ull a, ull b, ull c) {
    ull d; asm("fma.rn.f32x2 %0, %1, %2, %3;" : "=l"(d) : "l"(a), "l"(b), "l"(c)); return d;
}
__device__ __forceinline__ ull mul2(ull a, ull b) {
    ull d; asm("mul.rn.f32x2 %0, %1, %2;" : "=l"(d) : "l"(a), "l"(b)); return d;
}
__device__ __forceinline__ float tf32r(float x) {
    unsigned u; asm("cvt.rna.tf32.f32 %0, %1;" : "=r"(u) : "f"(x));
    return __uint_as_float(u);
}
__device__ __forceinline__ uint32_t smem_u32(const void* p) {
    uint32_t a;
    asm("{ .reg .u64 t; cvta.to.shared.u64 t, %1; cvt.u32.u64 %0, t; }" : "=r"(a) : "l"(p));
    return a;
}
__device__ __forceinline__ void cp16(uint32_t dst, const void* src) {
    asm volatile("cp.async.cg.shared.global [%0], [%1], 16;" :: "r"(dst), "l"(src) : "memory");
}

// fragment-major index for A element (b, k)
__device__ __forceinline__ int a_idx(int b, int k) {
    int mt = b >> 4, row = b & 15, ks = k >> 3, kc = k & 7;
    int lane = ((row & 7) << 2) | (kc & 3);
    int slot = ((kc >> 2) << 1) | (row >> 3);
    return (mt * KSTEPS + ks) * 128 + lane * 4 + slot;
}

// ---------------------------------------------------------------------------
// Stage 0: w_out [NOUT][KF] -> g_WF fragment-major (tf32-rounded, zero pad)
// ---------------------------------------------------------------------------
__global__ __launch_bounds__(256) void wt_kernel(const float* __restrict__ W)
{
    int i = blockIdx.x * 256 + threadIdx.x;
    if (i >= (NP / 8) * KSTEPS * 64) return;
    int n8 = i / (KSTEPS * 64);
    int r  = i - n8 * (KSTEPS * 64);
    int ks = r >> 6, q = r & 63;
    int lane = q >> 1, slot = q & 1;
    int n = n8 * 8 + (lane >> 2);
    int k = ks * 8 + (lane & 3) + 4 * slot;
    g_WF[i] = (n < NOUT && k < KF) ? tf32r(W[n * KF + k]) : 0.f;
}

// ---------------------------------------------------------------------------
// Stage 1: conv + max. ring[24], 12 batched independent LDG.64s per block
// (MLP=12), then 12 compute steps. Two adjacent channels packed per thread.
// ---------------------------------------------------------------------------
template<int S, bool C1, bool C2, bool C3>
__device__ __forceinline__ void comp_step(
    ull (&ring)[24],
    const ull* __restrict__ wa, const ull* __restrict__ wb, const ull* __restrict__ wc,
    float& m1a, float& m1b, float& m2a, float& m2b, float& m3a, float& m3b)
{
    float x, y;
    if (C1) {
        ull s = mul2(wa[0], ring[(S + 22) % 24]);
        s = fma2(wa[1], ring[(S + 23) % 24], s);
        s = fma2(wa[2], ring[S], s);
        unpk(s, x, y); m1a = fmaxf(m1a, x); m1b = fmaxf(m1b, y);
    }
    if (C2) {
        ull s = mul2(wb[0], ring[(S + 19) % 24]);
        #pragma unroll
        for (int i = 1; i < 6; i++) s = fma2(wb[i], ring[(S + 19 + i) % 24], s);
        unpk(s, x, y); m2a = fmaxf(m2a, x); m2b = fmaxf(m2b, y);
    }
    if (C3) {
        ull s = mul2(wc[0], ring[(S + 13) % 24]);
        #pragma unroll
        for (int i = 1; i < 12; i++) s = fma2(wc[i], ring[(S + 13 + i) % 24], s);
        unpk(s, x, y); m3a = fmaxf(m3a, x); m3b = fmaxf(m3b, y);
    }
}

__global__ __launch_bounds__(256) void conv_max_kernel(
    const float* __restrict__ seq,
    const float* __restrict__ w1, const float* __restrict__ b1,
    const float* __restrict__ w2, const float* __restrict__ b2,
    const float* __restrict__ w3, const float* __restrict__ b3,
    int nthreads)
{
    const int t = blockIdx.x * 256 + threadIdx.x;
    if (t >= nthreads) return;
    const int b  = t / 25;
    const int p  = t - b * 25;
    const int c0 = 2 * p, c1 = 2 * p + 1;

    const float* base = seq + (size_t)b * (LEN * XD) + c0;

    ull wa[3], wb[6], wc[12];
    #pragma unroll
    for (int i = 0; i < 3;  i++) wa[i] = pk(w1[3 * c0 + i],  w1[3 * c1 + i]);
    #pragma unroll
    for (int i = 0; i < 6;  i++) wb[i] = pk(w2[6 * c0 + i],  w2[6 * c1 + i]);
    #pragma unroll
    for (int i = 0; i < 12; i++) wc[i] = pk(w3[12 * c0 + i], w3[12 * c1 + i]);

    ull ring[24];
    float m1a = -INFINITY, m1b = -INFINITY;
    float m2a = -INFINITY, m2b = -INFINITY;
    float m3a = -INFINITY, m3b = -INFINITY;

    #define LS(S, L)  ring[S] = *(const ull*)(base + (L) * XD)
    #define CS(S, A, Bf, C) \
        comp_step<S, A, Bf, C>(ring, wa, wb, wc, m1a, m1b, m2a, m2b, m3a, m3b)

    // prologue: batch-load l=0..11, then partial computes
    LS(0, 0);  LS(1, 1);  LS(2, 2);  LS(3, 3);  LS(4, 4);  LS(5, 5);
    LS(6, 6);  LS(7, 7);  LS(8, 8);  LS(9, 9);  LS(10, 10); LS(11, 11);
    CS(2,  true, false, false);
    CS(3,  true, false, false);
    CS(4,  true, false, false);
    CS(5,  true, true,  false);
    CS(6,  true, true,  false);
    CS(7,  true, true,  false);
    CS(8,  true, true,  false);
    CS(9,  true, true,  false);
    CS(10, true, true,  false);
    CS(11, true, true,  true);

    // main: positions 12..227 in 9 blocks of 24
    const float* bp = base + 12 * XD;
    #pragma unroll 1
    for (int blk = 0; blk < 9; blk++, bp += 24 * XD) {
        ring[12] = *(const ull*)(bp + 0 * XD);
        ring[13] = *(const ull*)(bp + 1 * XD);
        ring[14] = *(const ull*)(bp + 2 * XD);
        ring[15] = *(const ull*)(bp + 3 * XD);
        ring[16] = *(const ull*)(bp + 4 * XD);
        ring[17] = *(const ull*)(bp + 5 * XD);
        ring[18] = *(const ull*)(bp + 6 * XD);
        ring[19] = *(const ull*)(bp + 7 * XD);
        ring[20] = *(const ull*)(bp + 8 * XD);
        ring[21] = *(const ull*)(bp + 9 * XD);
        ring[22] = *(const ull*)(bp + 10 * XD);
        ring[23] = *(const ull*)(bp + 11 * XD);
        CS(12, true, true, true); CS(13, true, true, true);
        CS(14, true, true, true); CS(15, true, true, true);
        CS(16, true, true, true); CS(17, true, true, true);
        CS(18, true, true, true); CS(19, true, true, true);
        CS(20, true, true, true); CS(21, true, true, true);
        CS(22, true, true, true); CS(23, true, true, true);
        ring[0]  = *(const ull*)(bp + 12 * XD);
        ring[1]  = *(const ull*)(bp + 13 * XD);
        ring[2]  = *(const ull*)(bp + 14 * XD);
        ring[3]  = *(const ull*)(bp + 15 * XD);
        ring[4]  = *(const ull*)(bp + 16 * XD);
        ring[5]  = *(const ull*)(bp + 17 * XD);
        ring[6]  = *(const ull*)(bp + 18 * XD);
        ring[7]  = *(const ull*)(bp + 19 * XD);
        ring[8]  = *(const ull*)(bp + 20 * XD);
        ring[9]  = *(const ull*)(bp + 21 * XD);
        ring[10] = *(const ull*)(bp + 22 * XD);
        ring[11] = *(const ull*)(bp + 23 * XD);
        CS(0, true, true, true); CS(1, true, true, true);
        CS(2, true, true, true); CS(3, true, true, true);
        CS(4, true, true, true); CS(5, true, true, true);
        CS(6, true, true, true); CS(7, true, true, true);
        CS(8, true, true, true); CS(9, true, true, true);
        CS(10, true, true, true); CS(11, true, true, true);
    }
    // tail: l = 228 (slot 12), 229 (slot 13)
    LS(12, 228); LS(13, 229);
    CS(12, true, true, true);
    CS(13, true, true, true);
    #undef LS
    #undef CS

    g_flatF[a_idx(b, 3 * c0 + 0)] = tf32r(m1a + b1[c0]);
    g_flatF[a_idx(b, 3 * c0 + 1)] = tf32r(m2a + b2[c0]);
    g_flatF[a_idx(b, 3 * c0 + 2)] = tf32r(m3a + b3[c0]);
    g_flatF[a_idx(b, 3 * c1 + 0)] = tf32r(m1b + b1[c1]);
    g_flatF[a_idx(b, 3 * c1 + 1)] = tf32r(m2b + b2[c1]);
    g_flatF[a_idx(b, 3 * c1 + 2)] = tf32r(m3b + b3[c1]);
    if (p < 5) {
        g_flatF[a_idx(b, KF + 2 * p)]     = 0.f;
        g_flatF[a_idx(b, KF + 2 * p + 1)] = 0.f;
    }
}

// ---------------------------------------------------------------------------
// Stage 2: tf32 mma.sync GEMM, cp.async double-buffered over 4 K-chunks of
// 5 ksteps. CTA 128x128, 8 warps 2x4, warp tile 64x32. 80KB smem -> 2 CTA/SM.
// ---------------------------------------------------------------------------
#define CH_A 1280            // float4 per chunk (A): 8*5*128/4
#define CH_B 1280            // float4 per chunk (B): 16*5*64/4
#define BUF_F4 (CH_A + CH_B) // 2560 float4 = 40KB
#define SMEM_SZ (2 * BUF_F4 * 16)   // 80KB

__device__ __forceinline__ void mma_tf32_16n8k8(
    float& c0, float& c1, float& c2, float& c3,
    uint32_t a0, uint32_t a1, uint32_t a2, uint32_t a3,
    uint32_t b0, uint32_t b1)
{
    asm volatile(
        "mma.sync.aligned.m16n8k8.row.col.f32.tf32.tf32.f32 "
        "{%0,%1,%2,%3}, {%4,%5,%6,%7}, {%8,%9}, {%0,%1,%2,%3};"
        : "+f"(c0), "+f"(c1), "+f"(c2), "+f"(c3)
        : "r"(a0), "r"(a1), "r"(a2), "r"(a3), "r"(b0), "r"(b1));
}

__global__ __launch_bounds__(256, 2)
void mma_kernel(const float* __restrict__ bias, float* __restrict__ out, int nbat)
{
    extern __shared__ float smem[];
    const uint32_t sb = smem_u32(smem);
    const int tid  = threadIdx.x;
    const int warp = tid >> 5, lane = tid & 31;
    const int wm = warp & 1, wn = warp >> 1;   // 2 x 4 warps
    const int bm = blockIdx.y * 128, bn = blockIdx.x * 128;
    const int mtg = bm >> 4, ntg = bn >> 3;

    const float4* gA = (const float4*)g_flatF;
    const float4* gB = (const float4*)g_WF;

    // prefetch chunk c into buffer buf
    auto prefetch = [&](int c, int buf) {
        uint32_t dbase = sb + buf * (BUF_F4 * 16);
        #pragma unroll
        for (int rep = 0; rep < 10; rep++) {
            int i = tid + rep * 256;
            if (i < CH_A) {
                int mt = i / 160, r = i - mt * 160;
                cp16(dbase + i * 16, gA + (size_t)((mtg + mt) * KSTEPS + c * 5) * 32 + r);
            } else {
                int j = i - CH_A;
                int nt = j / 80, r = j - nt * 80;
                cp16(dbase + i * 16, gB + (size_t)((ntg + nt) * KSTEPS + c * 5) * 16 + r);
            }
        }
        asm volatile("cp.async.commit_group;" ::: "memory");
    };

    float acc[4][4][4];
    #pragma unroll
    for (int i = 0; i < 4; i++)
        #pragma unroll
        for (int j = 0; j < 4; j++)
            #pragma unroll
            for (int r = 0; r < 4; r++) acc[i][j][r] = 0.f;

    prefetch(0, 0);
    #pragma unroll
    for (int c = 0; c < 4; c++) {
        if (c < 3) prefetch(c + 1, (c + 1) & 1);
        if (c < 3) asm volatile("cp.async.wait_group 1;" ::: "memory");
        else       asm volatile("cp.async.wait_group 0;" ::: "memory");
        __syncthreads();

        const float* buf = smem + (c & 1) * (BUF_F4 * 4);
        const float* sA = buf;
        const float* sB = buf + CH_A * 4;
        #pragma unroll
        for (int ks = 0; ks < 5; ks++) {
            uint32_t a[4][4], b[4][2];
            #pragma unroll
            for (int mt = 0; mt < 4; mt++) {
                float4 v = *(const float4*)(sA + ((wm * 4 + mt) * 5 + ks) * 128 + lane * 4);
                a[mt][0] = __float_as_uint(v.x); a[mt][1] = __float_as_uint(v.y);
                a[mt][2] = __float_as_uint(v.z); a[mt][3] = __float_as_uint(v.w);
            }
            #pragma unroll
            for (int nt = 0; nt < 4; nt++) {
                float2 v = *(const float2*)(sB + ((wn * 4 + nt) * 5 + ks) * 64 + lane * 2);
                b[nt][0] = __float_as_uint(v.x); b[nt][1] = __float_as_uint(v.y);
            }
            #pragma unroll
            for (int mt = 0; mt < 4; mt++)
                #pragma unroll
                for (int nt = 0; nt < 4; nt++)
                    mma_tf32_16n8k8(acc[mt][nt][0], acc[mt][nt][1],
                                    acc[mt][nt][2], acc[mt][nt][3],
                                    a[mt][0], a[mt][1], a[mt][2], a[mt][3],
                                    b[nt][0], b[nt][1]);
        }
        __syncthreads();
    }

    // epilogue: c0=(g,2t), c1=(g,2t+1), c2=(g+8,2t), c3=(g+8,2t+1)
    const int g  = lane >> 2;
    const int tg = lane & 3;
    #pragma unroll
    for (int mt = 0; mt < 4; mt++) {
        int row0 = bm + wm * 64 + mt * 16 + g;
        int row1 = row0 + 8;
        #pragma unroll
        for (int nt = 0; nt < 4; nt++) {
            int col = bn + wn * 32 + nt * 8 + 2 * tg;
            if (col < NOUT) {
                float2 bb = *(const float2*)(bias + col);
                if (row0 < nbat) {
                    float2 v = {acc[mt][nt][0] + bb.x, acc[mt][nt][1] + bb.y};
                    *(float2*)(out + (size_t)row0 * NOUT + col) = v;
                }
                if (row1 < nbat) {
                    float2 v = {acc[mt][nt][2] + bb.x, acc[mt][nt][3] + bb.y};
                    *(float2*)(out + (size_t)row1 * NOUT + col) = v;
                }
            }
        }
    }
}

// ---------------------------------------------------------------------------
extern "C" void kernel_launch(void* const* d_in, const int* in_sizes, int n_in,
                              void* d_out, int out_size)
{
    const float* seq   = (const float*)d_in[0];
    const float* w1    = (const float*)d_in[1];
    const float* b1    = (const float*)d_in[2];
    const float* w2    = (const float*)d_in[3];
    const float* b2    = (const float*)d_in[4];
    const float* w3    = (const float*)d_in[5];
    const float* b3    = (const float*)d_in[6];
    const float* w_out = (const float*)d_in[7];
    const float* b_out = (const float*)d_in[8];
    float* out = (float*)d_out;

    const int B = in_sizes[0] / (LEN * XD);
    const int nthreads = B * 25;

    static int smem_set = 0;
    if (!smem_set) {
        cudaFuncSetAttribute(mma_kernel, cudaFuncAttributeMaxDynamicSharedMemorySize, SMEM_SZ);
        smem_set = 1;
    }

    // conv first so the profiler's sampled slot lands on it
    conv_max_kernel<<<(nthreads + 255) / 256, 256>>>(seq, w1, b1, w2, b2, w3, b3, nthreads);
    wt_kernel<<<((NP / 8) * KSTEPS * 64 + 255) / 256, 256>>>(w_out);

    dim3 grid(NP / 128, (B + 127) / 128);
    mma_kernel<<<grid, 256, SMEM_SZ>>>(b_out, out, B);
}

// round 8
// speedup vs baseline: 3.5547x; 1.1233x over previous
#include <cuda_runtime.h>
#include <math.h>
#include <stdint.h>

#define XD    50
#define LEN   230
#define KF    150
#define KSTEPS 20          // K padded to 160 = 20 x 8
#define NOUT  1380
#define NP    1408
#define BTOT  16384

typedef unsigned long long ull;

// A fragment-major: [mtile(16 rows)][kstep(8 cols)][lane*4+slot]
__device__ __align__(16) float g_flatF[(BTOT / 16) * KSTEPS * 128];
// B fragment-major: [n8tile][kstep][lane*2+slot]
__device__ __align__(16) float g_WF[(NP / 8) * KSTEPS * 64];

// ---------------- helpers ----------------
__device__ __forceinline__ ull pk(float lo, float hi) {
    ull r; asm("mov.b64 %0, {%1, %2};" : "=l"(r) : "f"(lo), "f"(hi)); return r;
}
__device__ __forceinline__ void unpk(ull v, float& lo, float& hi) {
    asm("mov.b64 {%0, %1}, %2;" : "=f"(lo), "=f"(hi) : "l"(v));
}
__device__ __forceinline__ ull fma2(ull a, ull b, ull c) {
    ull d; asm("fma.rn.f32x2 %0, %1, %2, %3;" : "=l"(d) : "l"(a), "l"(b), "l"(c)); return d;
}
__device__ __forceinline__ ull mul2(ull a, ull b) {
    ull d; asm("mul.rn.f32x2 %0, %1, %2;" : "=l"(d) : "l"(a), "l"(b)); return d;
}
__device__ __forceinline__ float tf32r(float x) {
    unsigned u; asm("cvt.rna.tf32.f32 %0, %1;" : "=r"(u) : "f"(x));
    return __uint_as_float(u);
}
__device__ __forceinline__ uint32_t smem_u32(const void* p) {
    uint32_t a;
    asm("{ .reg .u64 t; cvta.to.shared.u64 t, %1; cvt.u32.u64 %0, t; }" : "=r"(a) : "l"(p));
    return a;
}
__device__ __forceinline__ void cp16(uint32_t dst, const void* src) {
    asm volatile("cp.async.cg.shared.global [%0], [%1], 16;" :: "r"(dst), "l"(src) : "memory");
}

// fragment-major index for A element (b, k)
__device__ __forceinline__ int a_idx(int b, int k) {
    int mt = b >> 4, row = b & 15, ks = k >> 3, kc = k & 7;
    int lane = ((row & 7) << 2) | (kc & 3);
    int slot = ((kc >> 2) << 1) | (row >> 3);
    return (mt * KSTEPS + ks) * 128 + lane * 4 + slot;
}

// ---------------------------------------------------------------------------
// Stage 0: w_out [NOUT][KF] -> g_WF fragment-major (tf32-rounded, zero pad)
// ---------------------------------------------------------------------------
__global__ __launch_bounds__(256) void wt_kernel(const float* __restrict__ W)
{
    int i = blockIdx.x * 256 + threadIdx.x;
    if (i >= (NP / 8) * KSTEPS * 64) return;
    int n8 = i / (KSTEPS * 64);
    int r  = i - n8 * (KSTEPS * 64);
    int ks = r >> 6, q = r & 63;
    int lane = q >> 1, slot = q & 1;
    int n = n8 * 8 + (lane >> 2);
    int k = ks * 8 + (lane & 3) + 4 * slot;
    g_WF[i] = (n < NOUT && k < KF) ? tf32r(W[n * KF + k]) : 0.f;
}

// ---------------------------------------------------------------------------
// Stage 1: conv + max, ring[24]. Schedule: compute(p); load(p+13) -> every
// load leads its first consumer by 13 positions (slot (p+13)%24 is freed by
// compute(p)). Two adjacent channels per thread packed as f32x2.
// ---------------------------------------------------------------------------
template<int S, bool C1, bool C2, bool C3>
__device__ __forceinline__ void comp_step(
    ull (&ring)[24],
    const ull* __restrict__ wa, const ull* __restrict__ wb, const ull* __restrict__ wc,
    float& m1a, float& m1b, float& m2a, float& m2b, float& m3a, float& m3b)
{
    float x, y;
    if (C1) {
        ull s = mul2(wa[0], ring[(S + 22) % 24]);
        s = fma2(wa[1], ring[(S + 23) % 24], s);
        s = fma2(wa[2], ring[S], s);
        unpk(s, x, y); m1a = fmaxf(m1a, x); m1b = fmaxf(m1b, y);
    }
    if (C2) {
        ull s = mul2(wb[0], ring[(S + 19) % 24]);
        #pragma unroll
        for (int i = 1; i < 6; i++) s = fma2(wb[i], ring[(S + 19 + i) % 24], s);
        unpk(s, x, y); m2a = fmaxf(m2a, x); m2b = fmaxf(m2b, y);
    }
    if (C3) {
        ull s = mul2(wc[0], ring[(S + 13) % 24]);
        #pragma unroll
        for (int i = 1; i < 12; i++) s = fma2(wc[i], ring[(S + 13 + i) % 24], s);
        unpk(s, x, y); m3a = fmaxf(m3a, x); m3b = fmaxf(m3b, y);
    }
}

__global__ __launch_bounds__(256) void conv_max_kernel(
    const float* __restrict__ seq,
    const float* __restrict__ w1, const float* __restrict__ b1,
    const float* __restrict__ w2, const float* __restrict__ b2,
    const float* __restrict__ w3, const float* __restrict__ b3,
    int nthreads)
{
    const int t = blockIdx.x * 256 + threadIdx.x;
    if (t >= nthreads) return;
    const int b  = t / 25;
    const int p  = t - b * 25;
    const int c0 = 2 * p, c1 = 2 * p + 1;

    const float* base = seq + (size_t)b * (LEN * XD) + c0;

    ull wa[3], wb[6], wc[12];
    #pragma unroll
    for (int i = 0; i < 3;  i++) wa[i] = pk(w1[3 * c0 + i],  w1[3 * c1 + i]);
    #pragma unroll
    for (int i = 0; i < 6;  i++) wb[i] = pk(w2[6 * c0 + i],  w2[6 * c1 + i]);
    #pragma unroll
    for (int i = 0; i < 12; i++) wc[i] = pk(w3[12 * c0 + i], w3[12 * c1 + i]);

    ull ring[24];
    float m1a = -INFINITY, m1b = -INFINITY;
    float m2a = -INFINITY, m2b = -INFINITY;
    float m3a = -INFINITY, m3b = -INFINITY;

    #define LS(S, L)  ring[S] = *(const ull*)(base + (L) * XD)
    #define CS(S, A, Bf, C) \
        comp_step<S, A, Bf, C>(ring, wa, wb, wc, m1a, m1b, m2a, m2b, m3a, m3b)

    // initial fill: positions 0..12 -> slots 0..12 (MLP=13)
    LS(0, 0);  LS(1, 1);  LS(2, 2);  LS(3, 3);  LS(4, 4);  LS(5, 5);  LS(6, 6);
    LS(7, 7);  LS(8, 8);  LS(9, 9);  LS(10, 10); LS(11, 11); LS(12, 12);

    // prologue p = 0..10: partial convs; each step prefetches p+13
    LS(13, 13);                                   // p=0
    LS(14, 14);                                   // p=1
    CS(2,  true, false, false); LS(15, 15);
    CS(3,  true, false, false); LS(16, 16);
    CS(4,  true, false, false); LS(17, 17);
    CS(5,  true, true,  false); LS(18, 18);
    CS(6,  true, true,  false); LS(19, 19);
    CS(7,  true, true,  false); LS(20, 20);
    CS(8,  true, true,  false); LS(21, 21);
    CS(9,  true, true,  false); LS(22, 22);
    CS(10, true, true,  false); LS(23, 23);

    // main: p = 11..202, 8 blocks of 24. step: CS(p); LS((p+13)%24, p+13)
    const float* bp = base + 11 * XD;   // position p0 = 11 + 24*blk
    #define M(S, OFF) \
        CS(S, true, true, true); \
        ring[(S + 13) % 24] = *(const ull*)(bp + (OFF + 13) * XD)
    #pragma unroll 1
    for (int blk = 0; blk < 8; blk++, bp += 24 * XD) {
        M(11, 0);  M(12, 1);  M(13, 2);  M(14, 3);  M(15, 4);  M(16, 5);
        M(17, 6);  M(18, 7);  M(19, 8);  M(20, 9);  M(21, 10); M(22, 11);
        M(23, 12); M(0, 13);  M(1, 14);  M(2, 15);  M(3, 16);  M(4, 17);
        M(5, 18);  M(6, 19);  M(7, 20);  M(8, 21);  M(9, 22);  M(10, 23);
    }
    #undef M

    // tail: p = 203..216 with loads (216..229), then p = 217..229 compute-only
    CS(11, true, true, true); LS(0, 216);
    CS(12, true, true, true); LS(1, 217);
    CS(13, true, true, true); LS(2, 218);
    CS(14, true, true, true); LS(3, 219);
    CS(15, true, true, true); LS(4, 220);
    CS(16, true, true, true); LS(5, 221);
    CS(17, true, true, true); LS(6, 222);
    CS(18, true, true, true); LS(7, 223);
    CS(19, true, true, true); LS(8, 224);
    CS(20, true, true, true); LS(9, 225);
    CS(21, true, true, true); LS(10, 226);
    CS(22, true, true, true); LS(11, 227);
    CS(23, true, true, true); LS(12, 228);
    CS(0,  true, true, true); LS(13, 229);
    CS(1,  true, true, true);
    CS(2,  true, true, true);
    CS(3,  true, true, true);
    CS(4,  true, true, true);
    CS(5,  true, true, true);
    CS(6,  true, true, true);
    CS(7,  true, true, true);
    CS(8,  true, true, true);
    CS(9,  true, true, true);
    CS(10, true, true, true);
    CS(11, true, true, true);
    CS(12, true, true, true);
    CS(13, true, true, true);
    #undef LS
    #undef CS

    g_flatF[a_idx(b, 3 * c0 + 0)] = tf32r(m1a + b1[c0]);
    g_flatF[a_idx(b, 3 * c0 + 1)] = tf32r(m2a + b2[c0]);
    g_flatF[a_idx(b, 3 * c0 + 2)] = tf32r(m3a + b3[c0]);
    g_flatF[a_idx(b, 3 * c1 + 0)] = tf32r(m1b + b1[c1]);
    g_flatF[a_idx(b, 3 * c1 + 1)] = tf32r(m2b + b2[c1]);
    g_flatF[a_idx(b, 3 * c1 + 2)] = tf32r(m3b + b3[c1]);
    if (p < 5) {
        g_flatF[a_idx(b, KF + 2 * p)]     = 0.f;
        g_flatF[a_idx(b, KF + 2 * p + 1)] = 0.f;
    }
}

// ---------------------------------------------------------------------------
// Stage 2: tf32 mma.sync GEMM, cp.async double-buffered over 4 K-chunks of
// 5 ksteps. CTA 128x128, 8 warps 2x4, warp tile 64x32. 80KB smem -> 2 CTA/SM.
// ---------------------------------------------------------------------------
#define CH_A 1280            // float4 per chunk (A): 8*5*128/4
#define CH_B 1280            // float4 per chunk (B): 16*5*64/4
#define BUF_F4 (CH_A + CH_B) // 2560 float4 = 40KB
#define SMEM_SZ (2 * BUF_F4 * 16)   // 80KB

__device__ __forceinline__ void mma_tf32_16n8k8(
    float& c0, float& c1, float& c2, float& c3,
    uint32_t a0, uint32_t a1, uint32_t a2, uint32_t a3,
    uint32_t b0, uint32_t b1)
{
    asm volatile(
        "mma.sync.aligned.m16n8k8.row.col.f32.tf32.tf32.f32 "
        "{%0,%1,%2,%3}, {%4,%5,%6,%7}, {%8,%9}, {%0,%1,%2,%3};"
        : "+f"(c0), "+f"(c1), "+f"(c2), "+f"(c3)
        : "r"(a0), "r"(a1), "r"(a2), "r"(a3), "r"(b0), "r"(b1));
}

__global__ __launch_bounds__(256, 2)
void mma_kernel(const float* __restrict__ bias, float* __restrict__ out, int nbat)
{
    extern __shared__ float smem[];
    const uint32_t sb = smem_u32(smem);
    const int tid  = threadIdx.x;
    const int warp = tid >> 5, lane = tid & 31;
    const int wm = warp & 1, wn = warp >> 1;   // 2 x 4 warps
    const int bm = blockIdx.y * 128, bn = blockIdx.x * 128;
    const int mtg = bm >> 4, ntg = bn >> 3;

    const float4* gA = (const float4*)g_flatF;
    const float4* gB = (const float4*)g_WF;

    auto prefetch = [&](int c, int buf) {
        uint32_t dbase = sb + buf * (BUF_F4 * 16);
        #pragma unroll
        for (int rep = 0; rep < 10; rep++) {
            int i = tid + rep * 256;
            if (i < CH_A) {
                int mt = i / 160, r = i - mt * 160;
                cp16(dbase + i * 16, gA + (size_t)((mtg + mt) * KSTEPS + c * 5) * 32 + r);
            } else {
                int j = i - CH_A;
                int nt = j / 80, r = j - nt * 80;
                cp16(dbase + i * 16, gB + (size_t)((ntg + nt) * KSTEPS + c * 5) * 16 + r);
            }
        }
        asm volatile("cp.async.commit_group;" ::: "memory");
    };

    float acc[4][4][4];
    #pragma unroll
    for (int i = 0; i < 4; i++)
        #pragma unroll
        for (int j = 0; j < 4; j++)
            #pragma unroll
            for (int r = 0; r < 4; r++) acc[i][j][r] = 0.f;

    prefetch(0, 0);
    #pragma unroll
    for (int c = 0; c < 4; c++) {
        if (c < 3) prefetch(c + 1, (c + 1) & 1);
        if (c < 3) asm volatile("cp.async.wait_group 1;" ::: "memory");
        else       asm volatile("cp.async.wait_group 0;" ::: "memory");
        __syncthreads();

        const float* buf = smem + (c & 1) * (BUF_F4 * 4);
        const float* sA = buf;
        const float* sB = buf + CH_A * 4;
        #pragma unroll
        for (int ks = 0; ks < 5; ks++) {
            uint32_t a[4][4], b[4][2];
            #pragma unroll
            for (int mt = 0; mt < 4; mt++) {
                float4 v = *(const float4*)(sA + ((wm * 4 + mt) * 5 + ks) * 128 + lane * 4);
                a[mt][0] = __float_as_uint(v.x); a[mt][1] = __float_as_uint(v.y);
                a[mt][2] = __float_as_uint(v.z); a[mt][3] = __float_as_uint(v.w);
            }
            #pragma unroll
            for (int nt = 0; nt < 4; nt++) {
                float2 v = *(const float2*)(sB + ((wn * 4 + nt) * 5 + ks) * 64 + lane * 2);
                b[nt][0] = __float_as_uint(v.x); b[nt][1] = __float_as_uint(v.y);
            }
            #pragma unroll
            for (int mt = 0; mt < 4; mt++)
                #pragma unroll
                for (int nt = 0; nt < 4; nt++)
                    mma_tf32_16n8k8(acc[mt][nt][0], acc[mt][nt][1],
                                    acc[mt][nt][2], acc[mt][nt][3],
                                    a[mt][0], a[mt][1], a[mt][2], a[mt][3],
                                    b[nt][0], b[nt][1]);
        }
        __syncthreads();
    }

    const int g  = lane >> 2;
    const int tg = lane & 3;
    #pragma unroll
    for (int mt = 0; mt < 4; mt++) {
        int row0 = bm + wm * 64 + mt * 16 + g;
        int row1 = row0 + 8;
        #pragma unroll
        for (int nt = 0; nt < 4; nt++) {
            int col = bn + wn * 32 + nt * 8 + 2 * tg;
            if (col < NOUT) {
                float2 bb = *(const float2*)(bias + col);
                if (row0 < nbat) {
                    float2 v = {acc[mt][nt][0] + bb.x, acc[mt][nt][1] + bb.y};
                    *(float2*)(out + (size_t)row0 * NOUT + col) = v;
                }
                if (row1 < nbat) {
                    float2 v = {acc[mt][nt][2] + bb.x, acc[mt][nt][3] + bb.y};
                    *(float2*)(out + (size_t)row1 * NOUT + col) = v;
                }
            }
        }
    }
}

// ---------------------------------------------------------------------------
extern "C" void kernel_launch(void* const* d_in, const int* in_sizes, int n_in,
                              void* d_out, int out_size)
{
    const float* seq   = (const float*)d_in[0];
    const float* w1    = (const float*)d_in[1];
    const float* b1    = (const float*)d_in[2];
    const float* w2    = (const float*)d_in[3];
    const float* b2    = (const float*)d_in[4];
    const float* w3    = (const float*)d_in[5];
    const float* b3    = (const float*)d_in[6];
    const float* w_out = (const float*)d_in[7];
    const float* b_out = (const float*)d_in[8];
    float* out = (float*)d_out;

    const int B = in_sizes[0] / (LEN * XD);
    const int nthreads = B * 25;

    static int smem_set = 0;
    if (!smem_set) {
        cudaFuncSetAttribute(mma_kernel, cudaFuncAttributeMaxDynamicSharedMemorySize, SMEM_SZ);
        smem_set = 1;
    }

    conv_max_kernel<<<(nthreads + 255) / 256, 256>>>(seq, w1, b1, w2, b2, w3, b3, nthreads);
    wt_kernel<<<((NP / 8) * KSTEPS * 64 + 255) / 256, 256>>>(w_out);

    dim3 grid(NP / 128, (B + 127) / 128);
    mma_kernel<<<grid, 256, SMEM_SZ>>>(b_out, out, B);
}